// round 11
// baseline (speedup 1.0000x reference)
#include <cuda_runtime.h>
#include <cuda_bf16.h>
#include <mma.h>
#include <cstdint>
#include <math.h>

using namespace nvcuda;

#define B_ 4096
#define S_ 32
#define F_ 256
#define E_ 256

#define BMT 64
#define BNT 64
#define SPAD 40          // bf16 elements per smem row (32 data + 8 pad)
#define BUFB (64 * SPAD) // elements per tile buffer

// ======================= scratch (__device__ globals) =======================
__device__ float SC_t [B_ * F_];          // t = M @ self (raw, c added in attn)
__device__ float SC_P [B_ * E_];          // final pre-activation (raw)
__device__ __nv_bfloat16 G_ymh[B_ * 2 * F_], G_yml[B_ * 2 * F_];  // [y|m] hi/lo

// precomputed operators, [N][K] K-major, hi/lo bf16 split
__device__ __nv_bfloat16 G_Mh[F_ * F_],   G_Ml[F_ * F_];       // M = Wk Wq^T
__device__ __nv_bfloat16 G_Wpch[E_ * 2 * F_], G_Wpcl[E_ * 2 * F_];  // [Wv@Wc_top | Wm@Wc_bot]^T
__device__ float G_c[F_];     // c = Wk bq
__device__ float G_pb[E_];    // pbias = bv@Wc_top + bm@Wc_bot + bc

__device__ __forceinline__ void bsplit(float x, __nv_bfloat16& h, __nv_bfloat16& l) {
    h = __float2bfloat16(x);
    l = __float2bfloat16(x - __bfloat162float(h));
}

// split two floats -> packed (h1:h0) and (l1:l0) uint32 (no address-of locals)
__device__ __forceinline__ void split2pack(float x0, float x1, uint32_t& ph, uint32_t& pl) {
    __nv_bfloat16 h0, l0, h1, l1;
    bsplit(x0, h0, l0);
    bsplit(x1, h1, l1);
    ph = (uint32_t)__bfloat16_as_ushort(h0) | ((uint32_t)__bfloat16_as_ushort(h1) << 16);
    pl = (uint32_t)__bfloat16_as_ushort(l0) | ((uint32_t)__bfloat16_as_ushort(l1) << 16);
}

__device__ __forceinline__ uint32_t smem_u32(const void* p) {
    uint32_t a;
    asm("{ .reg .u64 t; cvta.to.shared.u64 t, %1; cvt.u32.u64 %0, t; }" : "=r"(a) : "l"(p));
    return a;
}
__device__ __forceinline__ void cp16(uint32_t dst, const void* src) {
    asm volatile("cp.async.ca.shared.global [%0], [%1], 16;" :: "r"(dst), "l"(src) : "memory");
}
__device__ __forceinline__ void cp_commit() { asm volatile("cp.async.commit_group;" ::: "memory"); }
__device__ __forceinline__ void cp_wait0()  { asm volatile("cp.async.wait_group 0;" ::: "memory"); }

// ======================= prep: M, Wpc, c, pbias =============================
__global__ void __launch_bounds__(256) k_prep(const float* __restrict__ Wm,
                                              const float* __restrict__ Wv,
                                              const float* __restrict__ Wc,
                                              const float* __restrict__ Wk,
                                              const float* __restrict__ Wq,
                                              const float* __restrict__ bq,
                                              const float* __restrict__ bv,
                                              const float* __restrict__ bm,
                                              const float* __restrict__ bc)
{
    const int z = blockIdx.z;
    const int r = threadIdx.x >> 5, cc = threadIdx.x & 31;

    if (z == 0) {
        // M[f][x] = sum_e Wk[f,e] * Wq[x,e]
        const int f0 = blockIdx.x * 32, x0 = blockIdx.y * 32;
        __shared__ float tK[32][33], tQ[32][33];
        float acc[4] = {0.f, 0.f, 0.f, 0.f};
        for (int e0 = 0; e0 < 256; e0 += 32) {
#pragma unroll
            for (int i = 0; i < 4; i++) {
                tK[r + 8 * i][cc] = Wk[(size_t)(f0 + r + 8 * i) * 256 + e0 + cc];
                tQ[r + 8 * i][cc] = Wq[(size_t)(x0 + r + 8 * i) * 256 + e0 + cc];
            }
            __syncthreads();
#pragma unroll
            for (int j = 0; j < 4; j++) {
                float s = 0.f;
#pragma unroll
                for (int ee = 0; ee < 32; ee++)
                    s += tK[r + 8 * j][ee] * tQ[cc][ee];
                acc[j] += s;
            }
            __syncthreads();
        }
#pragma unroll
        for (int j = 0; j < 4; j++)
            bsplit(acc[j], G_Mh[(size_t)(f0 + r + 8 * j) * 256 + x0 + cc],
                           G_Ml[(size_t)(f0 + r + 8 * j) * 256 + x0 + cc]);
        return;
    }
    if (z == 1 || z == 2) {
        // Wpc[n][k(+256)] = sum_e Wx[k,e] * Wc[e(+256),n]   (z=1: Wv/top, z=2: Wm/bot)
        const float* Wx = (z == 1) ? Wv : Wm;
        const int erow0 = (z == 1) ? 0 : 256;
        const int kout0 = (z == 1) ? 0 : 256;
        const int n0 = blockIdx.x * 32, k0 = blockIdx.y * 32;
        __shared__ float tV[32][33], tC[32][33];
        float acc[4] = {0.f, 0.f, 0.f, 0.f};
        for (int e0 = 0; e0 < 256; e0 += 32) {
#pragma unroll
            for (int i = 0; i < 4; i++) {
                tV[r + 8 * i][cc] = Wx[(size_t)(k0 + r + 8 * i) * 256 + e0 + cc];
                tC[r + 8 * i][cc] = Wc[(size_t)(erow0 + e0 + r + 8 * i) * 256 + n0 + cc];
            }
            __syncthreads();
#pragma unroll
            for (int j = 0; j < 4; j++) {
                float s = 0.f;
#pragma unroll
                for (int ee = 0; ee < 32; ee++)
                    s += tV[cc][ee] * tC[ee][r + 8 * j];
                acc[j] += s;
            }
            __syncthreads();
        }
#pragma unroll
        for (int j = 0; j < 4; j++)
            bsplit(acc[j], G_Wpch[(size_t)(n0 + r + 8 * j) * 512 + kout0 + k0 + cc],
                           G_Wpcl[(size_t)(n0 + r + 8 * j) * 512 + kout0 + k0 + cc]);
        return;
    }
    // z == 3: vectors
    if (blockIdx.x == 0) {
        // c[f] = Wk[f,:] . bq ; blockIdx.y covers 32 f, each warp 4 f
        const int wid = r, lane = cc;
#pragma unroll
        for (int j = 0; j < 4; j++) {
            const int f = blockIdx.y * 32 + wid * 4 + j;
            float p = 0.f;
#pragma unroll
            for (int k = 0; k < 8; k++)
                p += Wk[(size_t)f * 256 + lane + 32 * k] * bq[lane + 32 * k];
#pragma unroll
            for (int o = 16; o; o >>= 1) p += __shfl_xor_sync(0xffffffffu, p, o);
            if (lane == 0) G_c[f] = p;
        }
    } else if (blockIdx.x == 1 && blockIdx.y == 0) {
        // pbias[j] = bc[j] + sum_i bv[i] Wc[i,j] + sum_i bm[i] Wc[256+i,j]
        const int j = threadIdx.x;
        float s = bc[j];
        for (int i = 0; i < 256; i++) s += bv[i] * Wc[(size_t)i * 256 + j];
        for (int i = 0; i < 256; i++) s += bm[i] * Wc[(size_t)(256 + i) * 256 + j];
        G_pb[j] = s;
    }
}

// ======================= WMMA GEMM core =====================================
// C[64x64 tile] = A @ B^T  (B = h+l bf16, stored [N][K] K-major)
// APRE:   A already bf16 hi/lo [M][K] -> pure cp.async path (no split work)
// GATHER: A row i = feat[ridx[m0+i]] (f32, split on the fly)
// 256 thr, 8 warps 4(M)x2(N), warp tile 16x32; BK=32; double-buffered;
// one __syncthreads per K-step; direct f32 wmma store.
template <bool APRE, bool GATHER>
__device__ __forceinline__ void gcore(const float* __restrict__ Af,
                                      const int* __restrict__ ridx,
                                      const __nv_bfloat16* __restrict__ Ah,
                                      const __nv_bfloat16* __restrict__ Al,
                                      const __nv_bfloat16* __restrict__ Bh,
                                      const __nv_bfloat16* __restrict__ Bl,
                                      float* __restrict__ C,
                                      int K, int ldc, int m0, int n0)
{
    __shared__ __align__(16) __nv_bfloat16 sAh[2][BUFB], sAl[2][BUFB];
    __shared__ __align__(16) __nv_bfloat16 sBh[2][BUFB], sBl[2][BUFB];

    const int tid = threadIdx.x, wid = tid >> 5;
    const int wm = wid & 3, wn = wid >> 2;
    const int lr = tid >> 2, lc = (tid & 3) * 8;   // loader: 64 rows x 4 thr/row

    wmma::fragment<wmma::accumulator, 16, 16, 16, float> acc[2];
    wmma::fill_fragment(acc[0], 0.0f);
    wmma::fill_fragment(acc[1], 0.0f);

    const uint32_t soff = (uint32_t)(lr * SPAD + lc) * 2;
    const uint32_t uAh0 = smem_u32(&sAh[0][0]) + soff;
    const uint32_t uAl0 = smem_u32(&sAl[0][0]) + soff;
    const uint32_t uBh0 = smem_u32(&sBh[0][0]) + soff;
    const uint32_t uBl0 = smem_u32(&sBl[0][0]) + soff;
    const size_t   bsrc = (size_t)(n0 + lr) * K + lc;
    const size_t   arow = GATHER ? (size_t)ridx[m0 + lr] * K : (size_t)(m0 + lr) * K;
    const size_t   asrc = arow + lc;

    cp16(uBh0, Bh + bsrc);
    cp16(uBl0, Bl + bsrc);
    if (APRE) {
        cp16(uAh0, Ah + asrc);
        cp16(uAl0, Al + asrc);
    }
    cp_commit();
    float4 a0, a1;
    if (!APRE) {
        a0 = *(const float4*)(Af + asrc);
        a1 = *(const float4*)(Af + asrc + 4);
    }

    const int n_iter = K >> 5;
    for (int ch = 0; ch < n_iter; ch++) {
        const int buf = ch & 1;
        if (!APRE) {
            uint4 uh, ul;
            split2pack(a0.x, a0.y, uh.x, ul.x);
            split2pack(a0.z, a0.w, uh.y, ul.y);
            split2pack(a1.x, a1.y, uh.z, ul.z);
            split2pack(a1.z, a1.w, uh.w, ul.w);
            *(uint4*)&sAh[buf][lr * SPAD + lc] = uh;
            *(uint4*)&sAl[buf][lr * SPAD + lc] = ul;
        }
        cp_wait0();
        __syncthreads();
        if (ch + 1 < n_iter) {
            const int k0 = (ch + 1) << 5;
            const uint32_t bo = (uint32_t)(buf ^ 1) * (BUFB * 2);
            cp16(uBh0 + bo, Bh + bsrc + k0);
            cp16(uBl0 + bo, Bl + bsrc + k0);
            if (APRE) {
                cp16(uAh0 + bo, Ah + asrc + k0);
                cp16(uAl0 + bo, Al + asrc + k0);
            } else {
                a0 = *(const float4*)(Af + asrc + k0);
                a1 = *(const float4*)(Af + asrc + k0 + 4);
            }
            cp_commit();
        }
#pragma unroll
        for (int kf = 0; kf < 2; kf++) {
            wmma::fragment<wmma::matrix_a, 16, 16, 16, __nv_bfloat16, wmma::row_major> ah, al;
            wmma::fragment<wmma::matrix_b, 16, 16, 16, __nv_bfloat16, wmma::col_major> bh[2], bl[2];
            wmma::load_matrix_sync(ah, &sAh[buf][(wm * 16) * SPAD + kf * 16], SPAD);
            wmma::load_matrix_sync(al, &sAl[buf][(wm * 16) * SPAD + kf * 16], SPAD);
#pragma unroll
            for (int ni = 0; ni < 2; ni++) {
                wmma::load_matrix_sync(bh[ni], &sBh[buf][(wn * 32 + ni * 16) * SPAD + kf * 16], SPAD);
                wmma::load_matrix_sync(bl[ni], &sBl[buf][(wn * 32 + ni * 16) * SPAD + kf * 16], SPAD);
            }
#pragma unroll
            for (int ni = 0; ni < 2; ni++) {
                wmma::mma_sync(acc[ni], ah, bh[ni], acc[ni]);
                wmma::mma_sync(acc[ni], ah, bl[ni], acc[ni]);
                wmma::mma_sync(acc[ni], al, bh[ni], acc[ni]);
            }
        }
    }
#pragma unroll
    for (int ni = 0; ni < 2; ni++)
        wmma::store_matrix_sync(&C[(size_t)(m0 + wm * 16) * ldc + n0 + wn * 32 + ni * 16],
                                acc[ni], ldc, wmma::mem_row_major);
}

// t = feat[nodes] @ M^T  (self-gather fused into the A loader)
__global__ void __launch_bounds__(256) k_tg(const int* __restrict__ nodes,
                                            const float* __restrict__ feat)
{
    gcore<false, true>(feat, nodes, nullptr, nullptr, G_Mh, G_Ml,
                       SC_t, 256, F_, blockIdx.y * BMT, blockIdx.x * BNT);
}
// P = ym @ Wpc^T  (K = 512, A pre-split bf16 -> all-async loads)
__global__ void __launch_bounds__(256) k_pg()
{
    gcore<true, false>(nullptr, nullptr, G_ymh, G_yml, G_Wpch, G_Wpcl,
                       SC_P, 512, E_, blockIdx.y * BMT, blockIdx.x * BNT);
}

// ======================= fused attention + mean aggregation ==================
// Mean-neighbor rows prefetched via cp.async (32 KB smem tile) overlapping the
// attention phase. Outputs ym as bf16 hi/lo (feeds the all-async k_pg).
__global__ void __launch_bounds__(256) k_attn(const int* __restrict__ neigh_attn,
                                              const int* __restrict__ neigh_mean,
                                              const float* __restrict__ feat)
{
    const int b = blockIdx.x;
    const int tid = threadIdx.x, wid = tid >> 5, lane = tid & 31;

    __shared__ int   idxA[S_], idxM[S_];
    __shared__ float sc[S_];
    __shared__ __align__(16) float part[8][256];
    __shared__ __align__(16) float meanT[S_][256];   // 32 KB prefetch tile

    if (tid < S_)           idxA[tid]      = neigh_attn[b * S_ + tid];
    else if (tid < 2 * S_)  idxM[tid - S_] = neigh_mean[b * S_ + tid - S_];

    // t (+c): lane holds cols [4l,4l+4) and [128+4l, 128+4l+4)
    float4 t0 = *(const float4*)&SC_t[b * F_ + lane * 4];
    float4 t1 = *(const float4*)&SC_t[b * F_ + 128 + lane * 4];
    const float4 c0 = *(const float4*)&G_c[lane * 4];
    const float4 c1 = *(const float4*)&G_c[128 + lane * 4];
    t0.x += c0.x; t0.y += c0.y; t0.z += c0.z; t0.w += c0.w;
    t1.x += c1.x; t1.y += c1.y; t1.z += c1.z; t1.w += c1.w;
    __syncthreads();

    // kick off mean-row prefetch (independent of attention) — 8 cp16/thread
    {
        const uint32_t mbase = smem_u32(&meanT[0][0]);
#pragma unroll
        for (int j = 0; j < 8; j++) {
            const int i = tid + 256 * j;           // 0..2047 float4 slots
            const int row = i >> 6, col4 = i & 63;
            cp16(mbase + (uint32_t)(row * 256 + col4 * 4) * 4,
                 feat + (size_t)idxM[row] * F_ + col4 * 4);
        }
        cp_commit();
    }

    // attention phase: warp w owns rows 4w..4w+3; coalesced LDG.128
    float4 x0[4], x1[4];
#pragma unroll
    for (int r = 0; r < 4; r++) {
        const float* row = feat + (size_t)idxA[wid * 4 + r] * F_;
        x0[r] = *(const float4*)(row + lane * 4);
        x1[r] = *(const float4*)(row + 128 + lane * 4);
    }
    float p[4];
#pragma unroll
    for (int r = 0; r < 4; r++)
        p[r] = x0[r].x * t0.x + x0[r].y * t0.y + x0[r].z * t0.z + x0[r].w * t0.w
             + x1[r].x * t1.x + x1[r].y * t1.y + x1[r].z * t1.z + x1[r].w * t1.w;
#pragma unroll
    for (int o = 16; o; o >>= 1)
#pragma unroll
        for (int r = 0; r < 4; r++)
            p[r] += __shfl_xor_sync(0xffffffffu, p[r], o);
    if (lane == 0) {
        sc[wid * 4 + 0] = p[0];
        sc[wid * 4 + 1] = p[1];
        sc[wid * 4 + 2] = p[2];
        sc[wid * 4 + 3] = p[3];
    }
    __syncthreads();

    // softmax over 32 neighbor scores (self slot masked out by construction)
    if (tid < 32) {
        const float v = sc[tid];
        float mx = v;
#pragma unroll
        for (int o = 16; o; o >>= 1) mx = fmaxf(mx, __shfl_xor_sync(0xffffffffu, mx, o));
        const float e = __expf(v - mx);
        float sum = e;
#pragma unroll
        for (int o = 16; o; o >>= 1) sum += __shfl_xor_sync(0xffffffffu, sum, o);
        sc[tid] = e / sum;
    }
    __syncthreads();

    const float a0 = sc[wid * 4 + 0], a1 = sc[wid * 4 + 1],
                a2 = sc[wid * 4 + 2], a3 = sc[wid * 4 + 3];
    float4 s0, s1;
    s0.x = a0 * x0[0].x + a1 * x0[1].x + a2 * x0[2].x + a3 * x0[3].x;
    s0.y = a0 * x0[0].y + a1 * x0[1].y + a2 * x0[2].y + a3 * x0[3].y;
    s0.z = a0 * x0[0].z + a1 * x0[1].z + a2 * x0[2].z + a3 * x0[3].z;
    s0.w = a0 * x0[0].w + a1 * x0[1].w + a2 * x0[2].w + a3 * x0[3].w;
    s1.x = a0 * x1[0].x + a1 * x1[1].x + a2 * x1[2].x + a3 * x1[3].x;
    s1.y = a0 * x1[0].y + a1 * x1[1].y + a2 * x1[2].y + a3 * x1[3].y;
    s1.z = a0 * x1[0].z + a1 * x1[1].z + a2 * x1[2].z + a3 * x1[3].z;
    s1.w = a0 * x1[0].w + a1 * x1[1].w + a2 * x1[2].w + a3 * x1[3].w;
    *(float4*)&part[wid][lane * 4]       = s0;
    *(float4*)&part[wid][128 + lane * 4] = s1;
    __syncthreads();

    float y = 0.f;
#pragma unroll
    for (int w = 0; w < 8; w++) y += part[w][tid];
    {
        __nv_bfloat16 h, l; bsplit(y, h, l);
        G_ymh[(size_t)b * 512 + tid] = h;
        G_yml[(size_t)b * 512 + tid] = l;
    }

    // mean phase: wait for prefetch, conflict-free column sum
    cp_wait0();
    __syncthreads();
    float m = 0.f;
#pragma unroll
    for (int r = 0; r < S_; r++) m += meanT[r][tid];
    {
        __nv_bfloat16 h, l; bsplit(m * (1.0f / S_), h, l);
        G_ymh[(size_t)b * 512 + 256 + tid] = h;
        G_yml[(size_t)b * 512 + 256 + tid] = l;
    }
}

// ======================= tanh(P + pbias) + L2 normalize ======================
__global__ void __launch_bounds__(256) k_norm(float* __restrict__ out)
{
    const int b = blockIdx.x, tid = threadIdx.x;
    const float v = tanhf(SC_P[b * E_ + tid] + G_pb[tid]);
    float ss = v * v;
    const int lane = tid & 31, wid = tid >> 5;
#pragma unroll
    for (int o = 16; o; o >>= 1) ss += __shfl_xor_sync(0xffffffffu, ss, o);
    __shared__ float red[8];
    if (lane == 0) red[wid] = ss;
    __syncthreads();
    float tot = 0.f;
#pragma unroll
    for (int i = 0; i < 8; i++) tot += red[i];
    const float scale = 1.0f / fmaxf(sqrtf(tot), 1e-12f);
    out[b * E_ + tid] = v * scale;
}

// ======================= host ===============================================
extern "C" void kernel_launch(void* const* d_in, const int* in_sizes, int n_in,
                              void* d_out, int out_size)
{
    const int*   nodes  = (const int*)  d_in[0];
    const int*   n_mean = (const int*)  d_in[1];
    const int*   n_attn = (const int*)  d_in[2];
    const float* feat   = (const float*)d_in[3];
    const float* Wm = (const float*)d_in[4],  *bm = (const float*)d_in[5];
    const float* Wq = (const float*)d_in[6],  *bq = (const float*)d_in[7];
    const float* Wk = (const float*)d_in[8];  // bk cancels in softmax
    const float* Wv = (const float*)d_in[10], *bv = (const float*)d_in[11];
    const float* Wc = (const float*)d_in[12], *bc = (const float*)d_in[13];
    float* out = (float*)d_out;

    const dim3 ggrid(E_ / BNT, B_ / BMT, 1);   // (4, 64) = 256 CTAs

    // 1) prep: M = Wk Wq^T, Wpc = [Wv@Wc_top | Wm@Wc_bot]^T, c, pbias
    k_prep<<<dim3(8, 8, 4), 256>>>(Wm, Wv, Wc, Wk, Wq, bq, bv, bm, bc);

    // 2) t = feat[nodes] @ M^T  (self gather fused)
    k_tg<<<ggrid, 256>>>(nodes, feat);

    // 3) fused attention + overlapped mean aggregation -> ym (bf16 hi/lo)
    k_attn<<<B_, 256>>>(n_attn, n_mean, feat);

    // 4) P = ym @ Wpc^T  (K = 512, all-async GEMM)
    k_pg<<<ggrid, 256>>>();

    // 5) out = L2-normalize(tanh(P + pbias))
    k_norm<<<B_, 256>>>(out);
}

// round 12
// speedup vs baseline: 1.0007x; 1.0007x over previous
#include <cuda_runtime.h>
#include <cuda_bf16.h>
#include <mma.h>
#include <cstdint>
#include <math.h>

using namespace nvcuda;

#define B_ 4096
#define S_ 32
#define F_ 256
#define E_ 256

#define BMT 64
#define BNT 64
#define SPAD 40          // bf16 elements per smem row (32 data + 8 pad)
#define BUFB (64 * SPAD) // elements per tile buffer

// ======================= scratch (__device__ globals) =======================
__device__ float SC_t [B_ * F_];          // t = M @ self (raw, c added in attn)
__device__ float SC_P [B_ * E_];          // final pre-activation (raw)
__device__ __nv_bfloat16 G_ymh[B_ * 2 * F_], G_yml[B_ * 2 * F_];  // [y|m] hi/lo

// precomputed operators, [N][K] K-major, hi/lo bf16 split
__device__ __nv_bfloat16 G_Mh[F_ * F_],   G_Ml[F_ * F_];       // M = Wk Wq^T
__device__ __nv_bfloat16 G_Wpch[E_ * 2 * F_], G_Wpcl[E_ * 2 * F_];  // [Wv@Wc_top | Wm@Wc_bot]^T
__device__ float G_c[F_];     // c = Wk bq
__device__ float G_pb[E_];    // pbias = bv@Wc_top + bm@Wc_bot + bc

__device__ __forceinline__ void bsplit(float x, __nv_bfloat16& h, __nv_bfloat16& l) {
    h = __float2bfloat16(x);
    l = __float2bfloat16(x - __bfloat162float(h));
}

// split two floats -> packed (h1:h0) and (l1:l0) uint32 (no address-of locals)
__device__ __forceinline__ void split2pack(float x0, float x1, uint32_t& ph, uint32_t& pl) {
    __nv_bfloat16 h0, l0, h1, l1;
    bsplit(x0, h0, l0);
    bsplit(x1, h1, l1);
    ph = (uint32_t)__bfloat16_as_ushort(h0) | ((uint32_t)__bfloat16_as_ushort(h1) << 16);
    pl = (uint32_t)__bfloat16_as_ushort(l0) | ((uint32_t)__bfloat16_as_ushort(l1) << 16);
}

__device__ __forceinline__ uint32_t smem_u32(const void* p) {
    uint32_t a;
    asm("{ .reg .u64 t; cvta.to.shared.u64 t, %1; cvt.u32.u64 %0, t; }" : "=r"(a) : "l"(p));
    return a;
}
__device__ __forceinline__ void cp16(uint32_t dst, const void* src) {
    asm volatile("cp.async.ca.shared.global [%0], [%1], 16;" :: "r"(dst), "l"(src) : "memory");
}
__device__ __forceinline__ void cp_commit() { asm volatile("cp.async.commit_group;" ::: "memory"); }
__device__ __forceinline__ void cp_wait0()  { asm volatile("cp.async.wait_group 0;" ::: "memory"); }

// ======================= prep: M, Wpc, c, pbias =============================
__global__ void __launch_bounds__(256) k_prep(const float* __restrict__ Wm,
                                              const float* __restrict__ Wv,
                                              const float* __restrict__ Wc,
                                              const float* __restrict__ Wk,
                                              const float* __restrict__ Wq,
                                              const float* __restrict__ bq,
                                              const float* __restrict__ bv,
                                              const float* __restrict__ bm,
                                              const float* __restrict__ bc)
{
    const int z = blockIdx.z;
    const int r = threadIdx.x >> 5, cc = threadIdx.x & 31;

    if (z == 0) {
        // M[f][x] = sum_e Wk[f,e] * Wq[x,e]
        const int f0 = blockIdx.x * 32, x0 = blockIdx.y * 32;
        __shared__ float tK[32][33], tQ[32][33];
        float acc[4] = {0.f, 0.f, 0.f, 0.f};
        for (int e0 = 0; e0 < 256; e0 += 32) {
#pragma unroll
            for (int i = 0; i < 4; i++) {
                tK[r + 8 * i][cc] = Wk[(size_t)(f0 + r + 8 * i) * 256 + e0 + cc];
                tQ[r + 8 * i][cc] = Wq[(size_t)(x0 + r + 8 * i) * 256 + e0 + cc];
            }
            __syncthreads();
#pragma unroll
            for (int j = 0; j < 4; j++) {
                float s = 0.f;
#pragma unroll
                for (int ee = 0; ee < 32; ee++)
                    s += tK[r + 8 * j][ee] * tQ[cc][ee];
                acc[j] += s;
            }
            __syncthreads();
        }
#pragma unroll
        for (int j = 0; j < 4; j++)
            bsplit(acc[j], G_Mh[(size_t)(f0 + r + 8 * j) * 256 + x0 + cc],
                           G_Ml[(size_t)(f0 + r + 8 * j) * 256 + x0 + cc]);
        return;
    }
    if (z == 1 || z == 2) {
        // Wpc[n][k(+256)] = sum_e Wx[k,e] * Wc[e(+256),n]   (z=1: Wv/top, z=2: Wm/bot)
        const float* Wx = (z == 1) ? Wv : Wm;
        const int erow0 = (z == 1) ? 0 : 256;
        const int kout0 = (z == 1) ? 0 : 256;
        const int n0 = blockIdx.x * 32, k0 = blockIdx.y * 32;
        __shared__ float tV[32][33], tC[32][33];
        float acc[4] = {0.f, 0.f, 0.f, 0.f};
        for (int e0 = 0; e0 < 256; e0 += 32) {
#pragma unroll
            for (int i = 0; i < 4; i++) {
                tV[r + 8 * i][cc] = Wx[(size_t)(k0 + r + 8 * i) * 256 + e0 + cc];
                tC[r + 8 * i][cc] = Wc[(size_t)(erow0 + e0 + r + 8 * i) * 256 + n0 + cc];
            }
            __syncthreads();
#pragma unroll
            for (int j = 0; j < 4; j++) {
                float s = 0.f;
#pragma unroll
                for (int ee = 0; ee < 32; ee++)
                    s += tV[cc][ee] * tC[ee][r + 8 * j];
                acc[j] += s;
            }
            __syncthreads();
        }
#pragma unroll
        for (int j = 0; j < 4; j++)
            bsplit(acc[j], G_Wpch[(size_t)(n0 + r + 8 * j) * 512 + kout0 + k0 + cc],
                           G_Wpcl[(size_t)(n0 + r + 8 * j) * 512 + kout0 + k0 + cc]);
        return;
    }
    // z == 3: vectors
    if (blockIdx.x == 0) {
        // c[f] = Wk[f,:] . bq ; blockIdx.y covers 32 f, each warp 4 f
        const int wid = r, lane = cc;
#pragma unroll
        for (int j = 0; j < 4; j++) {
            const int f = blockIdx.y * 32 + wid * 4 + j;
            float p = 0.f;
#pragma unroll
            for (int k = 0; k < 8; k++)
                p += Wk[(size_t)f * 256 + lane + 32 * k] * bq[lane + 32 * k];
#pragma unroll
            for (int o = 16; o; o >>= 1) p += __shfl_xor_sync(0xffffffffu, p, o);
            if (lane == 0) G_c[f] = p;
        }
    } else if (blockIdx.x == 1 && blockIdx.y == 0) {
        // pbias[j] = bc[j] + sum_i bv[i] Wc[i,j] + sum_i bm[i] Wc[256+i,j]
        const int j = threadIdx.x;
        float s = bc[j];
        for (int i = 0; i < 256; i++) s += bv[i] * Wc[(size_t)i * 256 + j];
        for (int i = 0; i < 256; i++) s += bm[i] * Wc[(size_t)(256 + i) * 256 + j];
        G_pb[j] = s;
    }
}

// ======================= WMMA GEMM core =====================================
// C[64x64 tile] = A @ B^T  (B = h+l bf16, stored [N][K] K-major)
// APRE:   A already bf16 hi/lo [M][K] -> pure cp.async path (no split work)
// GATHER: A row i = feat[ridx[m0+i]] (f32, split on the fly)
// 256 thr, 8 warps 4(M)x2(N), warp tile 16x32; BK=32; double-buffered;
// one __syncthreads per K-step; direct f32 wmma store.
template <bool APRE, bool GATHER>
__device__ __forceinline__ void gcore(const float* __restrict__ Af,
                                      const int* __restrict__ ridx,
                                      const __nv_bfloat16* __restrict__ Ah,
                                      const __nv_bfloat16* __restrict__ Al,
                                      const __nv_bfloat16* __restrict__ Bh,
                                      const __nv_bfloat16* __restrict__ Bl,
                                      float* __restrict__ C,
                                      int K, int ldc, int m0, int n0)
{
    __shared__ __align__(16) __nv_bfloat16 sAh[2][BUFB], sAl[2][BUFB];
    __shared__ __align__(16) __nv_bfloat16 sBh[2][BUFB], sBl[2][BUFB];

    const int tid = threadIdx.x, wid = tid >> 5;
    const int wm = wid & 3, wn = wid >> 2;
    const int lr = tid >> 2, lc = (tid & 3) * 8;   // loader: 64 rows x 4 thr/row

    wmma::fragment<wmma::accumulator, 16, 16, 16, float> acc[2];
    wmma::fill_fragment(acc[0], 0.0f);
    wmma::fill_fragment(acc[1], 0.0f);

    const uint32_t soff = (uint32_t)(lr * SPAD + lc) * 2;
    const uint32_t uAh0 = smem_u32(&sAh[0][0]) + soff;
    const uint32_t uAl0 = smem_u32(&sAl[0][0]) + soff;
    const uint32_t uBh0 = smem_u32(&sBh[0][0]) + soff;
    const uint32_t uBl0 = smem_u32(&sBl[0][0]) + soff;
    const size_t   bsrc = (size_t)(n0 + lr) * K + lc;
    const size_t   arow = GATHER ? (size_t)ridx[m0 + lr] * K : (size_t)(m0 + lr) * K;
    const size_t   asrc = arow + lc;

    cp16(uBh0, Bh + bsrc);
    cp16(uBl0, Bl + bsrc);
    if (APRE) {
        cp16(uAh0, Ah + asrc);
        cp16(uAl0, Al + asrc);
    }
    cp_commit();
    float4 a0, a1;
    if (!APRE) {
        a0 = *(const float4*)(Af + asrc);
        a1 = *(const float4*)(Af + asrc + 4);
    }

    const int n_iter = K >> 5;
    for (int ch = 0; ch < n_iter; ch++) {
        const int buf = ch & 1;
        if (!APRE) {
            uint4 uh, ul;
            split2pack(a0.x, a0.y, uh.x, ul.x);
            split2pack(a0.z, a0.w, uh.y, ul.y);
            split2pack(a1.x, a1.y, uh.z, ul.z);
            split2pack(a1.z, a1.w, uh.w, ul.w);
            *(uint4*)&sAh[buf][lr * SPAD + lc] = uh;
            *(uint4*)&sAl[buf][lr * SPAD + lc] = ul;
        }
        cp_wait0();
        __syncthreads();
        if (ch + 1 < n_iter) {
            const int k0 = (ch + 1) << 5;
            const uint32_t bo = (uint32_t)(buf ^ 1) * (BUFB * 2);
            cp16(uBh0 + bo, Bh + bsrc + k0);
            cp16(uBl0 + bo, Bl + bsrc + k0);
            if (APRE) {
                cp16(uAh0 + bo, Ah + asrc + k0);
                cp16(uAl0 + bo, Al + asrc + k0);
            } else {
                a0 = *(const float4*)(Af + asrc + k0);
                a1 = *(const float4*)(Af + asrc + k0 + 4);
            }
            cp_commit();
        }
#pragma unroll
        for (int kf = 0; kf < 2; kf++) {
            wmma::fragment<wmma::matrix_a, 16, 16, 16, __nv_bfloat16, wmma::row_major> ah, al;
            wmma::fragment<wmma::matrix_b, 16, 16, 16, __nv_bfloat16, wmma::col_major> bh[2], bl[2];
            wmma::load_matrix_sync(ah, &sAh[buf][(wm * 16) * SPAD + kf * 16], SPAD);
            wmma::load_matrix_sync(al, &sAl[buf][(wm * 16) * SPAD + kf * 16], SPAD);
#pragma unroll
            for (int ni = 0; ni < 2; ni++) {
                wmma::load_matrix_sync(bh[ni], &sBh[buf][(wn * 32 + ni * 16) * SPAD + kf * 16], SPAD);
                wmma::load_matrix_sync(bl[ni], &sBl[buf][(wn * 32 + ni * 16) * SPAD + kf * 16], SPAD);
            }
#pragma unroll
            for (int ni = 0; ni < 2; ni++) {
                wmma::mma_sync(acc[ni], ah, bh[ni], acc[ni]);
                wmma::mma_sync(acc[ni], ah, bl[ni], acc[ni]);
                wmma::mma_sync(acc[ni], al, bh[ni], acc[ni]);
            }
        }
    }
#pragma unroll
    for (int ni = 0; ni < 2; ni++)
        wmma::store_matrix_sync(&C[(size_t)(m0 + wm * 16) * ldc + n0 + wn * 32 + ni * 16],
                                acc[ni], ldc, wmma::mem_row_major);
}

// t = feat[nodes] @ M^T  (self-gather fused into the A loader)
__global__ void __launch_bounds__(256) k_tg(const int* __restrict__ nodes,
                                            const float* __restrict__ feat)
{
    gcore<false, true>(feat, nodes, nullptr, nullptr, G_Mh, G_Ml,
                       SC_t, 256, F_, blockIdx.y * BMT, blockIdx.x * BNT);
}
// P = ym @ Wpc^T  (K = 512, A pre-split bf16 -> all-async loads)
__global__ void __launch_bounds__(256) k_pg()
{
    gcore<true, false>(nullptr, nullptr, G_ymh, G_yml, G_Wpch, G_Wpcl,
                       SC_P, 512, E_, blockIdx.y * BMT, blockIdx.x * BNT);
}

// ======================= fused attention + mean aggregation ==================
// Mean-neighbor rows prefetched via cp.async (32 KB smem tile) overlapping the
// attention phase. Outputs ym as bf16 hi/lo (feeds the all-async k_pg).
__global__ void __launch_bounds__(256) k_attn(const int* __restrict__ neigh_attn,
                                              const int* __restrict__ neigh_mean,
                                              const float* __restrict__ feat)
{
    const int b = blockIdx.x;
    const int tid = threadIdx.x, wid = tid >> 5, lane = tid & 31;

    __shared__ int   idxA[S_], idxM[S_];
    __shared__ float sc[S_];
    __shared__ __align__(16) float part[8][256];
    __shared__ __align__(16) float meanT[S_][256];   // 32 KB prefetch tile

    if (tid < S_)           idxA[tid]      = neigh_attn[b * S_ + tid];
    else if (tid < 2 * S_)  idxM[tid - S_] = neigh_mean[b * S_ + tid - S_];

    // t (+c): lane holds cols [4l,4l+4) and [128+4l, 128+4l+4)
    float4 t0 = *(const float4*)&SC_t[b * F_ + lane * 4];
    float4 t1 = *(const float4*)&SC_t[b * F_ + 128 + lane * 4];
    const float4 c0 = *(const float4*)&G_c[lane * 4];
    const float4 c1 = *(const float4*)&G_c[128 + lane * 4];
    t0.x += c0.x; t0.y += c0.y; t0.z += c0.z; t0.w += c0.w;
    t1.x += c1.x; t1.y += c1.y; t1.z += c1.z; t1.w += c1.w;
    __syncthreads();

    // kick off mean-row prefetch (independent of attention) — 8 cp16/thread
    {
        const uint32_t mbase = smem_u32(&meanT[0][0]);
#pragma unroll
        for (int j = 0; j < 8; j++) {
            const int i = tid + 256 * j;           // 0..2047 float4 slots
            const int row = i >> 6, col4 = i & 63;
            cp16(mbase + (uint32_t)(row * 256 + col4 * 4) * 4,
                 feat + (size_t)idxM[row] * F_ + col4 * 4);
        }
        cp_commit();
    }

    // attention phase: warp w owns rows 4w..4w+3; coalesced LDG.128
    float4 x0[4], x1[4];
#pragma unroll
    for (int r = 0; r < 4; r++) {
        const float* row = feat + (size_t)idxA[wid * 4 + r] * F_;
        x0[r] = *(const float4*)(row + lane * 4);
        x1[r] = *(const float4*)(row + 128 + lane * 4);
    }
    float p[4];
#pragma unroll
    for (int r = 0; r < 4; r++)
        p[r] = x0[r].x * t0.x + x0[r].y * t0.y + x0[r].z * t0.z + x0[r].w * t0.w
             + x1[r].x * t1.x + x1[r].y * t1.y + x1[r].z * t1.z + x1[r].w * t1.w;
#pragma unroll
    for (int o = 16; o; o >>= 1)
#pragma unroll
        for (int r = 0; r < 4; r++)
            p[r] += __shfl_xor_sync(0xffffffffu, p[r], o);
    if (lane == 0) {
        sc[wid * 4 + 0] = p[0];
        sc[wid * 4 + 1] = p[1];
        sc[wid * 4 + 2] = p[2];
        sc[wid * 4 + 3] = p[3];
    }
    __syncthreads();

    // softmax over 32 neighbor scores (self slot masked out by construction)
    if (tid < 32) {
        const float v = sc[tid];
        float mx = v;
#pragma unroll
        for (int o = 16; o; o >>= 1) mx = fmaxf(mx, __shfl_xor_sync(0xffffffffu, mx, o));
        const float e = __expf(v - mx);
        float sum = e;
#pragma unroll
        for (int o = 16; o; o >>= 1) sum += __shfl_xor_sync(0xffffffffu, sum, o);
        sc[tid] = e / sum;
    }
    __syncthreads();

    const float a0 = sc[wid * 4 + 0], a1 = sc[wid * 4 + 1],
                a2 = sc[wid * 4 + 2], a3 = sc[wid * 4 + 3];
    float4 s0, s1;
    s0.x = a0 * x0[0].x + a1 * x0[1].x + a2 * x0[2].x + a3 * x0[3].x;
    s0.y = a0 * x0[0].y + a1 * x0[1].y + a2 * x0[2].y + a3 * x0[3].y;
    s0.z = a0 * x0[0].z + a1 * x0[1].z + a2 * x0[2].z + a3 * x0[3].z;
    s0.w = a0 * x0[0].w + a1 * x0[1].w + a2 * x0[2].w + a3 * x0[3].w;
    s1.x = a0 * x1[0].x + a1 * x1[1].x + a2 * x1[2].x + a3 * x1[3].x;
    s1.y = a0 * x1[0].y + a1 * x1[1].y + a2 * x1[2].y + a3 * x1[3].y;
    s1.z = a0 * x1[0].z + a1 * x1[1].z + a2 * x1[2].z + a3 * x1[3].z;
    s1.w = a0 * x1[0].w + a1 * x1[1].w + a2 * x1[2].w + a3 * x1[3].w;
    *(float4*)&part[wid][lane * 4]       = s0;
    *(float4*)&part[wid][128 + lane * 4] = s1;
    __syncthreads();

    float y = 0.f;
#pragma unroll
    for (int w = 0; w < 8; w++) y += part[w][tid];
    {
        __nv_bfloat16 h, l; bsplit(y, h, l);
        G_ymh[(size_t)b * 512 + tid] = h;
        G_yml[(size_t)b * 512 + tid] = l;
    }

    // mean phase: wait for prefetch, conflict-free column sum
    cp_wait0();
    __syncthreads();
    float m = 0.f;
#pragma unroll
    for (int r = 0; r < S_; r++) m += meanT[r][tid];
    {
        __nv_bfloat16 h, l; bsplit(m * (1.0f / S_), h, l);
        G_ymh[(size_t)b * 512 + 256 + tid] = h;
        G_yml[(size_t)b * 512 + 256 + tid] = l;
    }
}

// ======================= tanh(P + pbias) + L2 normalize ======================
__global__ void __launch_bounds__(256) k_norm(float* __restrict__ out)
{
    const int b = blockIdx.x, tid = threadIdx.x;
    const float v = tanhf(SC_P[b * E_ + tid] + G_pb[tid]);
    float ss = v * v;
    const int lane = tid & 31, wid = tid >> 5;
#pragma unroll
    for (int o = 16; o; o >>= 1) ss += __shfl_xor_sync(0xffffffffu, ss, o);
    __shared__ float red[8];
    if (lane == 0) red[wid] = ss;
    __syncthreads();
    float tot = 0.f;
#pragma unroll
    for (int i = 0; i < 8; i++) tot += red[i];
    const float scale = 1.0f / fmaxf(sqrtf(tot), 1e-12f);
    out[b * E_ + tid] = v * scale;
}

// ======================= host ===============================================
extern "C" void kernel_launch(void* const* d_in, const int* in_sizes, int n_in,
                              void* d_out, int out_size)
{
    const int*   nodes  = (const int*)  d_in[0];
    const int*   n_mean = (const int*)  d_in[1];
    const int*   n_attn = (const int*)  d_in[2];
    const float* feat   = (const float*)d_in[3];
    const float* Wm = (const float*)d_in[4],  *bm = (const float*)d_in[5];
    const float* Wq = (const float*)d_in[6],  *bq = (const float*)d_in[7];
    const float* Wk = (const float*)d_in[8];  // bk cancels in softmax
    const float* Wv = (const float*)d_in[10], *bv = (const float*)d_in[11];
    const float* Wc = (const float*)d_in[12], *bc = (const float*)d_in[13];
    float* out = (float*)d_out;

    const dim3 ggrid(E_ / BNT, B_ / BMT, 1);   // (4, 64) = 256 CTAs

    // 1) prep: M = Wk Wq^T, Wpc = [Wv@Wc_top | Wm@Wc_bot]^T, c, pbias
    k_prep<<<dim3(8, 8, 4), 256>>>(Wm, Wv, Wc, Wk, Wq, bq, bv, bm, bc);

    // 2) t = feat[nodes] @ M^T  (self gather fused)
    k_tg<<<ggrid, 256>>>(nodes, feat);

    // 3) fused attention + overlapped mean aggregation -> ym (bf16 hi/lo)
    k_attn<<<B_, 256>>>(n_attn, n_mean, feat);

    // 4) P = ym @ Wpc^T  (K = 512, all-async GEMM)
    k_pg<<<ggrid, 256>>>();

    // 5) out = L2-normalize(tanh(P + pbias))
    k_norm<<<B_, 256>>>(out);
}

// round 13
// speedup vs baseline: 1.0010x; 1.0003x over previous
#include <cuda_runtime.h>
#include <cuda_bf16.h>
#include <mma.h>
#include <cstdint>
#include <math.h>

using namespace nvcuda;

#define B_ 4096
#define S_ 32
#define F_ 256
#define E_ 256

#define BMT 64
#define BNT 64
#define SPAD 40          // bf16 elements per smem row (32 data + 8 pad)
#define BUFB (64 * SPAD) // elements per tile buffer

// ======================= scratch (__device__ globals) =======================
__device__ float SC_t [B_ * F_];          // t = M @ self (raw, c added in attn)
__device__ float SC_P [B_ * E_];          // final pre-activation (raw)
__device__ __nv_bfloat16 G_ymh[B_ * 2 * F_], G_yml[B_ * 2 * F_];  // [y|m] hi/lo

// precomputed operators, [N][K] K-major, hi/lo bf16 split
__device__ __nv_bfloat16 G_Mh[F_ * F_],   G_Ml[F_ * F_];       // M = Wk Wq^T
__device__ __nv_bfloat16 G_Wpch[E_ * 2 * F_], G_Wpcl[E_ * 2 * F_];  // [Wv@Wc_top | Wm@Wc_bot]^T
__device__ float G_c[F_];     // c = Wk bq
__device__ float G_pb[E_];    // pbias = bv@Wc_top + bm@Wc_bot + bc

__device__ __forceinline__ void bsplit(float x, __nv_bfloat16& h, __nv_bfloat16& l) {
    h = __float2bfloat16(x);
    l = __float2bfloat16(x - __bfloat162float(h));
}

// split two floats -> packed (h1:h0) and (l1:l0) uint32 (no address-of locals)
__device__ __forceinline__ void split2pack(float x0, float x1, uint32_t& ph, uint32_t& pl) {
    __nv_bfloat16 h0, l0, h1, l1;
    bsplit(x0, h0, l0);
    bsplit(x1, h1, l1);
    ph = (uint32_t)__bfloat16_as_ushort(h0) | ((uint32_t)__bfloat16_as_ushort(h1) << 16);
    pl = (uint32_t)__bfloat16_as_ushort(l0) | ((uint32_t)__bfloat16_as_ushort(l1) << 16);
}

__device__ __forceinline__ uint32_t smem_u32(const void* p) {
    uint32_t a;
    asm("{ .reg .u64 t; cvta.to.shared.u64 t, %1; cvt.u32.u64 %0, t; }" : "=r"(a) : "l"(p));
    return a;
}
__device__ __forceinline__ void cp16(uint32_t dst, const void* src) {
    asm volatile("cp.async.ca.shared.global [%0], [%1], 16;" :: "r"(dst), "l"(src) : "memory");
}
__device__ __forceinline__ void cp_commit() { asm volatile("cp.async.commit_group;" ::: "memory"); }
__device__ __forceinline__ void cp_wait0()  { asm volatile("cp.async.wait_group 0;" ::: "memory"); }

// ======================= prep: M, Wpc, c, pbias =============================
__global__ void __launch_bounds__(256) k_prep(const float* __restrict__ Wm,
                                              const float* __restrict__ Wv,
                                              const float* __restrict__ Wc,
                                              const float* __restrict__ Wk,
                                              const float* __restrict__ Wq,
                                              const float* __restrict__ bq,
                                              const float* __restrict__ bv,
                                              const float* __restrict__ bm,
                                              const float* __restrict__ bc)
{
    const int z = blockIdx.z;
    const int r = threadIdx.x >> 5, cc = threadIdx.x & 31;

    if (z == 0) {
        // M[f][x] = sum_e Wk[f,e] * Wq[x,e]
        const int f0 = blockIdx.x * 32, x0 = blockIdx.y * 32;
        __shared__ float tK[32][33], tQ[32][33];
        float acc[4] = {0.f, 0.f, 0.f, 0.f};
        for (int e0 = 0; e0 < 256; e0 += 32) {
#pragma unroll
            for (int i = 0; i < 4; i++) {
                tK[r + 8 * i][cc] = Wk[(size_t)(f0 + r + 8 * i) * 256 + e0 + cc];
                tQ[r + 8 * i][cc] = Wq[(size_t)(x0 + r + 8 * i) * 256 + e0 + cc];
            }
            __syncthreads();
#pragma unroll
            for (int j = 0; j < 4; j++) {
                float s = 0.f;
#pragma unroll
                for (int ee = 0; ee < 32; ee++)
                    s += tK[r + 8 * j][ee] * tQ[cc][ee];
                acc[j] += s;
            }
            __syncthreads();
        }
#pragma unroll
        for (int j = 0; j < 4; j++)
            bsplit(acc[j], G_Mh[(size_t)(f0 + r + 8 * j) * 256 + x0 + cc],
                           G_Ml[(size_t)(f0 + r + 8 * j) * 256 + x0 + cc]);
        return;
    }
    if (z == 1 || z == 2) {
        // Wpc[n][k(+256)] = sum_e Wx[k,e] * Wc[e(+256),n]   (z=1: Wv/top, z=2: Wm/bot)
        const float* Wx = (z == 1) ? Wv : Wm;
        const int erow0 = (z == 1) ? 0 : 256;
        const int kout0 = (z == 1) ? 0 : 256;
        const int n0 = blockIdx.x * 32, k0 = blockIdx.y * 32;
        __shared__ float tV[32][33], tC[32][33];
        float acc[4] = {0.f, 0.f, 0.f, 0.f};
        for (int e0 = 0; e0 < 256; e0 += 32) {
#pragma unroll
            for (int i = 0; i < 4; i++) {
                tV[r + 8 * i][cc] = Wx[(size_t)(k0 + r + 8 * i) * 256 + e0 + cc];
                tC[r + 8 * i][cc] = Wc[(size_t)(erow0 + e0 + r + 8 * i) * 256 + n0 + cc];
            }
            __syncthreads();
#pragma unroll
            for (int j = 0; j < 4; j++) {
                float s = 0.f;
#pragma unroll
                for (int ee = 0; ee < 32; ee++)
                    s += tV[cc][ee] * tC[ee][r + 8 * j];
                acc[j] += s;
            }
            __syncthreads();
        }
#pragma unroll
        for (int j = 0; j < 4; j++)
            bsplit(acc[j], G_Wpch[(size_t)(n0 + r + 8 * j) * 512 + kout0 + k0 + cc],
                           G_Wpcl[(size_t)(n0 + r + 8 * j) * 512 + kout0 + k0 + cc]);
        return;
    }
    // z == 3: vectors
    if (blockIdx.x == 0) {
        // c[f] = Wk[f,:] . bq ; blockIdx.y covers 32 f, each warp 4 f
        const int wid = r, lane = cc;
#pragma unroll
        for (int j = 0; j < 4; j++) {
            const int f = blockIdx.y * 32 + wid * 4 + j;
            float p = 0.f;
#pragma unroll
            for (int k = 0; k < 8; k++)
                p += Wk[(size_t)f * 256 + lane + 32 * k] * bq[lane + 32 * k];
#pragma unroll
            for (int o = 16; o; o >>= 1) p += __shfl_xor_sync(0xffffffffu, p, o);
            if (lane == 0) G_c[f] = p;
        }
    } else if (blockIdx.x == 1 && blockIdx.y == 0) {
        // pbias[j] = bc[j] + sum_i bv[i] Wc[i,j] + sum_i bm[i] Wc[256+i,j]
        const int j = threadIdx.x;
        float s = bc[j];
        for (int i = 0; i < 256; i++) s += bv[i] * Wc[(size_t)i * 256 + j];
        for (int i = 0; i < 256; i++) s += bm[i] * Wc[(size_t)(256 + i) * 256 + j];
        G_pb[j] = s;
    }
}

// ======================= WMMA GEMM core =====================================
// C[64x64 tile] = A @ B^T  (B = h+l bf16, stored [N][K] K-major)
// APRE:   A already bf16 hi/lo [M][K] -> pure cp.async path (no split work)
// GATHER: A row i = feat[ridx[m0+i]] (f32, split on the fly)
// 256 thr, 8 warps 4(M)x2(N), warp tile 16x32; BK=32; double-buffered;
// one __syncthreads per K-step; direct f32 wmma store.
template <bool APRE, bool GATHER>
__device__ __forceinline__ void gcore(const float* __restrict__ Af,
                                      const int* __restrict__ ridx,
                                      const __nv_bfloat16* __restrict__ Ah,
                                      const __nv_bfloat16* __restrict__ Al,
                                      const __nv_bfloat16* __restrict__ Bh,
                                      const __nv_bfloat16* __restrict__ Bl,
                                      float* __restrict__ C,
                                      int K, int ldc, int m0, int n0)
{
    __shared__ __align__(16) __nv_bfloat16 sAh[2][BUFB], sAl[2][BUFB];
    __shared__ __align__(16) __nv_bfloat16 sBh[2][BUFB], sBl[2][BUFB];

    const int tid = threadIdx.x, wid = tid >> 5;
    const int wm = wid & 3, wn = wid >> 2;
    const int lr = tid >> 2, lc = (tid & 3) * 8;   // loader: 64 rows x 4 thr/row

    wmma::fragment<wmma::accumulator, 16, 16, 16, float> acc[2];
    wmma::fill_fragment(acc[0], 0.0f);
    wmma::fill_fragment(acc[1], 0.0f);

    const uint32_t soff = (uint32_t)(lr * SPAD + lc) * 2;
    const uint32_t uAh0 = smem_u32(&sAh[0][0]) + soff;
    const uint32_t uAl0 = smem_u32(&sAl[0][0]) + soff;
    const uint32_t uBh0 = smem_u32(&sBh[0][0]) + soff;
    const uint32_t uBl0 = smem_u32(&sBl[0][0]) + soff;
    const size_t   bsrc = (size_t)(n0 + lr) * K + lc;
    const size_t   arow = GATHER ? (size_t)ridx[m0 + lr] * K : (size_t)(m0 + lr) * K;
    const size_t   asrc = arow + lc;

    cp16(uBh0, Bh + bsrc);
    cp16(uBl0, Bl + bsrc);
    if (APRE) {
        cp16(uAh0, Ah + asrc);
        cp16(uAl0, Al + asrc);
    }
    cp_commit();
    float4 a0, a1;
    if (!APRE) {
        a0 = *(const float4*)(Af + asrc);
        a1 = *(const float4*)(Af + asrc + 4);
    }

    const int n_iter = K >> 5;
    for (int ch = 0; ch < n_iter; ch++) {
        const int buf = ch & 1;
        if (!APRE) {
            uint4 uh, ul;
            split2pack(a0.x, a0.y, uh.x, ul.x);
            split2pack(a0.z, a0.w, uh.y, ul.y);
            split2pack(a1.x, a1.y, uh.z, ul.z);
            split2pack(a1.z, a1.w, uh.w, ul.w);
            *(uint4*)&sAh[buf][lr * SPAD + lc] = uh;
            *(uint4*)&sAl[buf][lr * SPAD + lc] = ul;
        }
        cp_wait0();
        __syncthreads();
        if (ch + 1 < n_iter) {
            const int k0 = (ch + 1) << 5;
            const uint32_t bo = (uint32_t)(buf ^ 1) * (BUFB * 2);
            cp16(uBh0 + bo, Bh + bsrc + k0);
            cp16(uBl0 + bo, Bl + bsrc + k0);
            if (APRE) {
                cp16(uAh0 + bo, Ah + asrc + k0);
                cp16(uAl0 + bo, Al + asrc + k0);
            } else {
                a0 = *(const float4*)(Af + asrc + k0);
                a1 = *(const float4*)(Af + asrc + k0 + 4);
            }
            cp_commit();
        }
#pragma unroll
        for (int kf = 0; kf < 2; kf++) {
            wmma::fragment<wmma::matrix_a, 16, 16, 16, __nv_bfloat16, wmma::row_major> ah, al;
            wmma::fragment<wmma::matrix_b, 16, 16, 16, __nv_bfloat16, wmma::col_major> bh[2], bl[2];
            wmma::load_matrix_sync(ah, &sAh[buf][(wm * 16) * SPAD + kf * 16], SPAD);
            wmma::load_matrix_sync(al, &sAl[buf][(wm * 16) * SPAD + kf * 16], SPAD);
#pragma unroll
            for (int ni = 0; ni < 2; ni++) {
                wmma::load_matrix_sync(bh[ni], &sBh[buf][(wn * 32 + ni * 16) * SPAD + kf * 16], SPAD);
                wmma::load_matrix_sync(bl[ni], &sBl[buf][(wn * 32 + ni * 16) * SPAD + kf * 16], SPAD);
            }
#pragma unroll
            for (int ni = 0; ni < 2; ni++) {
                wmma::mma_sync(acc[ni], ah, bh[ni], acc[ni]);
                wmma::mma_sync(acc[ni], ah, bl[ni], acc[ni]);
                wmma::mma_sync(acc[ni], al, bh[ni], acc[ni]);
            }
        }
    }
#pragma unroll
    for (int ni = 0; ni < 2; ni++)
        wmma::store_matrix_sync(&C[(size_t)(m0 + wm * 16) * ldc + n0 + wn * 32 + ni * 16],
                                acc[ni], ldc, wmma::mem_row_major);
}

// t = feat[nodes] @ M^T  (self-gather fused into the A loader)
__global__ void __launch_bounds__(256) k_tg(const int* __restrict__ nodes,
                                            const float* __restrict__ feat)
{
    gcore<false, true>(feat, nodes, nullptr, nullptr, G_Mh, G_Ml,
                       SC_t, 256, F_, blockIdx.y * BMT, blockIdx.x * BNT);
}
// P = ym @ Wpc^T  (K = 512, A pre-split bf16 -> all-async loads)
__global__ void __launch_bounds__(256) k_pg()
{
    gcore<true, false>(nullptr, nullptr, G_ymh, G_yml, G_Wpch, G_Wpcl,
                       SC_P, 512, E_, blockIdx.y * BMT, blockIdx.x * BNT);
}

// ======================= fused attention + mean aggregation ==================
// Mean-neighbor rows prefetched via cp.async (32 KB smem tile) overlapping the
// attention phase. Outputs ym as bf16 hi/lo (feeds the all-async k_pg).
__global__ void __launch_bounds__(256) k_attn(const int* __restrict__ neigh_attn,
                                              const int* __restrict__ neigh_mean,
                                              const float* __restrict__ feat)
{
    const int b = blockIdx.x;
    const int tid = threadIdx.x, wid = tid >> 5, lane = tid & 31;

    __shared__ int   idxA[S_], idxM[S_];
    __shared__ float sc[S_];
    __shared__ __align__(16) float part[8][256];
    __shared__ __align__(16) float meanT[S_][256];   // 32 KB prefetch tile

    if (tid < S_)           idxA[tid]      = neigh_attn[b * S_ + tid];
    else if (tid < 2 * S_)  idxM[tid - S_] = neigh_mean[b * S_ + tid - S_];

    // t (+c): lane holds cols [4l,4l+4) and [128+4l, 128+4l+4)
    float4 t0 = *(const float4*)&SC_t[b * F_ + lane * 4];
    float4 t1 = *(const float4*)&SC_t[b * F_ + 128 + lane * 4];
    const float4 c0 = *(const float4*)&G_c[lane * 4];
    const float4 c1 = *(const float4*)&G_c[128 + lane * 4];
    t0.x += c0.x; t0.y += c0.y; t0.z += c0.z; t0.w += c0.w;
    t1.x += c1.x; t1.y += c1.y; t1.z += c1.z; t1.w += c1.w;
    __syncthreads();

    // kick off mean-row prefetch (independent of attention) — 8 cp16/thread
    {
        const uint32_t mbase = smem_u32(&meanT[0][0]);
#pragma unroll
        for (int j = 0; j < 8; j++) {
            const int i = tid + 256 * j;           // 0..2047 float4 slots
            const int row = i >> 6, col4 = i & 63;
            cp16(mbase + (uint32_t)(row * 256 + col4 * 4) * 4,
                 feat + (size_t)idxM[row] * F_ + col4 * 4);
        }
        cp_commit();
    }

    // attention phase: warp w owns rows 4w..4w+3; coalesced LDG.128
    float4 x0[4], x1[4];
#pragma unroll
    for (int r = 0; r < 4; r++) {
        const float* row = feat + (size_t)idxA[wid * 4 + r] * F_;
        x0[r] = *(const float4*)(row + lane * 4);
        x1[r] = *(const float4*)(row + 128 + lane * 4);
    }
    float p[4];
#pragma unroll
    for (int r = 0; r < 4; r++)
        p[r] = x0[r].x * t0.x + x0[r].y * t0.y + x0[r].z * t0.z + x0[r].w * t0.w
             + x1[r].x * t1.x + x1[r].y * t1.y + x1[r].z * t1.z + x1[r].w * t1.w;
#pragma unroll
    for (int o = 16; o; o >>= 1)
#pragma unroll
        for (int r = 0; r < 4; r++)
            p[r] += __shfl_xor_sync(0xffffffffu, p[r], o);
    if (lane == 0) {
        sc[wid * 4 + 0] = p[0];
        sc[wid * 4 + 1] = p[1];
        sc[wid * 4 + 2] = p[2];
        sc[wid * 4 + 3] = p[3];
    }
    __syncthreads();

    // softmax over 32 neighbor scores (self slot masked out by construction)
    if (tid < 32) {
        const float v = sc[tid];
        float mx = v;
#pragma unroll
        for (int o = 16; o; o >>= 1) mx = fmaxf(mx, __shfl_xor_sync(0xffffffffu, mx, o));
        const float e = __expf(v - mx);
        float sum = e;
#pragma unroll
        for (int o = 16; o; o >>= 1) sum += __shfl_xor_sync(0xffffffffu, sum, o);
        sc[tid] = e / sum;
    }
    __syncthreads();

    const float a0 = sc[wid * 4 + 0], a1 = sc[wid * 4 + 1],
                a2 = sc[wid * 4 + 2], a3 = sc[wid * 4 + 3];
    float4 s0, s1;
    s0.x = a0 * x0[0].x + a1 * x0[1].x + a2 * x0[2].x + a3 * x0[3].x;
    s0.y = a0 * x0[0].y + a1 * x0[1].y + a2 * x0[2].y + a3 * x0[3].y;
    s0.z = a0 * x0[0].z + a1 * x0[1].z + a2 * x0[2].z + a3 * x0[3].z;
    s0.w = a0 * x0[0].w + a1 * x0[1].w + a2 * x0[2].w + a3 * x0[3].w;
    s1.x = a0 * x1[0].x + a1 * x1[1].x + a2 * x1[2].x + a3 * x1[3].x;
    s1.y = a0 * x1[0].y + a1 * x1[1].y + a2 * x1[2].y + a3 * x1[3].y;
    s1.z = a0 * x1[0].z + a1 * x1[1].z + a2 * x1[2].z + a3 * x1[3].z;
    s1.w = a0 * x1[0].w + a1 * x1[1].w + a2 * x1[2].w + a3 * x1[3].w;
    *(float4*)&part[wid][lane * 4]       = s0;
    *(float4*)&part[wid][128 + lane * 4] = s1;
    __syncthreads();

    float y = 0.f;
#pragma unroll
    for (int w = 0; w < 8; w++) y += part[w][tid];
    {
        __nv_bfloat16 h, l; bsplit(y, h, l);
        G_ymh[(size_t)b * 512 + tid] = h;
        G_yml[(size_t)b * 512 + tid] = l;
    }

    // mean phase: wait for prefetch, conflict-free column sum
    cp_wait0();
    __syncthreads();
    float m = 0.f;
#pragma unroll
    for (int r = 0; r < S_; r++) m += meanT[r][tid];
    {
        __nv_bfloat16 h, l; bsplit(m * (1.0f / S_), h, l);
        G_ymh[(size_t)b * 512 + 256 + tid] = h;
        G_yml[(size_t)b * 512 + 256 + tid] = l;
    }
}

// ======================= tanh(P + pbias) + L2 normalize ======================
__global__ void __launch_bounds__(256) k_norm(float* __restrict__ out)
{
    const int b = blockIdx.x, tid = threadIdx.x;
    const float v = tanhf(SC_P[b * E_ + tid] + G_pb[tid]);
    float ss = v * v;
    const int lane = tid & 31, wid = tid >> 5;
#pragma unroll
    for (int o = 16; o; o >>= 1) ss += __shfl_xor_sync(0xffffffffu, ss, o);
    __shared__ float red[8];
    if (lane == 0) red[wid] = ss;
    __syncthreads();
    float tot = 0.f;
#pragma unroll
    for (int i = 0; i < 8; i++) tot += red[i];
    const float scale = 1.0f / fmaxf(sqrtf(tot), 1e-12f);
    out[b * E_ + tid] = v * scale;
}

// ======================= host ===============================================
extern "C" void kernel_launch(void* const* d_in, const int* in_sizes, int n_in,
                              void* d_out, int out_size)
{
    const int*   nodes  = (const int*)  d_in[0];
    const int*   n_mean = (const int*)  d_in[1];
    const int*   n_attn = (const int*)  d_in[2];
    const float* feat   = (const float*)d_in[3];
    const float* Wm = (const float*)d_in[4],  *bm = (const float*)d_in[5];
    const float* Wq = (const float*)d_in[6],  *bq = (const float*)d_in[7];
    const float* Wk = (const float*)d_in[8];  // bk cancels in softmax
    const float* Wv = (const float*)d_in[10], *bv = (const float*)d_in[11];
    const float* Wc = (const float*)d_in[12], *bc = (const float*)d_in[13];
    float* out = (float*)d_out;

    const dim3 ggrid(E_ / BNT, B_ / BMT, 1);   // (4, 64) = 256 CTAs

    // 1) prep: M = Wk Wq^T, Wpc = [Wv@Wc_top | Wm@Wc_bot]^T, c, pbias
    k_prep<<<dim3(8, 8, 4), 256>>>(Wm, Wv, Wc, Wk, Wq, bq, bv, bm, bc);

    // 2) t = feat[nodes] @ M^T  (self gather fused)
    k_tg<<<ggrid, 256>>>(nodes, feat);

    // 3) fused attention + overlapped mean aggregation -> ym (bf16 hi/lo)
    k_attn<<<B_, 256>>>(n_attn, n_mean, feat);

    // 4) P = ym @ Wpc^T  (K = 512, all-async GEMM)
    k_pg<<<ggrid, 256>>>();

    // 5) out = L2-normalize(tanh(P + pbias))
    k_norm<<<B_, 256>>>(out);
}